// round 15
// baseline (speedup 1.0000x reference)
#include <cuda_runtime.h>
#include <cuda_bf16.h>
#include <cuda_fp8.h>
#include <stdint.h>

#define HDIM   2048
#define SEQL   2048
#define NTOK   8188
#define NTOKP  8192
#define VOCABN 131072
#define NGRP   2
#define VPG    65536
#define NTILE  256
#define NTILES 256          // VPG / NTILE
#define KC     128          // K elems per kstep (128B rows, fp8)
#define KSTEPS 16           // HDIM / KC
#define NSUP   8            // superstages per tile (2 ksteps each)
#define NSTG   3            // slots
#define SSTG   65536        // per-slot bytes: A0 16K | W0 16K | A1 16K | W1 16K
#define THREADS 256
#define NSUP_TOT (NTILES * NSUP)   // 2048

#define WSCALE 32.0f
#define INVWS  0.03125f
#define LOG2E  1.44269504f
#define LN2    0.6931471805599453

#define OFF_BIAS  196608    // 2 x 1KB bias double buffer (pre-scaled by log2e)
#define OFF_CTRL  198656    // tmem ptr + mbarriers
#define SMEM_DYN  (198912 + 1024)

// idesc kind::f8f6f4: dtype F32 (bit4), e4m3, N=256 -> (32<<17), M=256 -> (2<<27)
#define IDESC_F8_CG2 0x10400010u

#if defined(__CUDA_ARCH_FEAT_SM103_ALL) || defined(__CUDA_ARCH_FEAT_SM100_ALL) || defined(__CUDA_ARCH_FEAT_SM101_ALL)
#define USE_TC 1
#else
#define USE_TC 0
#endif

// ------------ device scratch (static; allocation-free) ------------
__device__ uint8_t g_A[(size_t)NTOKP * HDIM];    // fp8 e4m3
__device__ uint8_t g_W[(size_t)VOCABN * HDIM];   // fp8 e4m3, pre-scaled by 32
__device__ int    g_lab[NTOKP];
__device__ float  g_pm[NGRP][NTOKP];
__device__ float  g_ps[NGRP][NTOKP];
__device__ float  g_pt[NGRP][NTOKP];  // log2-domain target logit

// ------------ PTX helpers ------------
__device__ __forceinline__ uint32_t smaddr(const void* p) {
    return (uint32_t)__cvta_generic_to_shared(p);
}
__device__ __forceinline__ float ex2f(float x) {
    float y;
    asm("ex2.approx.ftz.f32 %0, %1;" : "=f"(y) : "f"(x));
    return y;
}
__device__ __forceinline__ void cp16(uint32_t dst, const void* src) {
    asm volatile("cp.async.cg.shared.global [%0], [%1], 16;" :: "r"(dst), "l"(src) : "memory");
}
__device__ __forceinline__ uint32_t cluster_rank() {
    uint32_t r;
    asm("mov.u32 %0, %%cluster_ctarank;" : "=r"(r));
    return r;
}
#define CLUSTER_SYNC() do { \
    asm volatile("barrier.cluster.arrive.aligned;" ::: "memory"); \
    asm volatile("barrier.cluster.wait.aligned;" ::: "memory"); \
} while (0)

#define MBAR_INIT(a, c) \
    asm volatile("mbarrier.init.shared.b64 [%0], %1;" :: "r"(a), "r"(c) : "memory")
#define CPASYNC_MBAR_ARRIVE(a) \
    asm volatile("cp.async.mbarrier.arrive.noinc.shared::cta.b64 [%0];" :: "r"(a) : "memory")
// arrive on the LEADER CTA's barrier of the MMA pair (clear bit 24)
#define MBAR_ARRIVE_LEADER(a) \
    asm volatile("{\n\t.reg .b32 la;\n\tand.b32 la, %0, 0xFEFFFFFF;\n\t" \
                 "mbarrier.arrive.shared::cluster.b64 _, [la];\n\t}" \
                 :: "r"(a) : "memory")

#define MBAR_WAIT(addr, ph) do {                                               \
    uint32_t _a = (addr); uint32_t _p = (ph); uint32_t _d;                     \
    asm volatile("{\n\t.reg .pred p;\n\t"                                      \
        "mbarrier.try_wait.parity.acquire.cta.shared::cta.b64 p, [%1], %2;\n\t"\
        "selp.b32 %0, 1, 0, p;\n\t}" : "=r"(_d) : "r"(_a), "r"(_p) : "memory");\
    if (!_d) {                                                                 \
        asm volatile("{\n\t.reg .pred P1;\n\t"                                 \
            "WL_%=:\n\t"                                                       \
            "mbarrier.try_wait.parity.acquire.cta.shared::cta.b64 P1, [%0], %1, 0x989680;\n\t" \
            "@P1 bra.uni WD_%=;\n\t"                                           \
            "bra.uni WL_%=;\n\t"                                               \
            "WD_%=:\n\t}" :: "r"(_a), "r"(_p) : "memory");                     \
    }                                                                          \
} while (0)

// cluster-scope acquire (cross-CTA release/acquire pairing)
#define MBAR_WAIT_CL(addr, ph) do {                                            \
    uint32_t _a = (addr); uint32_t _p = (ph); uint32_t _d;                     \
    asm volatile("{\n\t.reg .pred p;\n\t"                                      \
        "mbarrier.try_wait.parity.acquire.cluster.shared::cta.b64 p, [%1], %2;\n\t"\
        "selp.b32 %0, 1, 0, p;\n\t}" : "=r"(_d) : "r"(_a), "r"(_p) : "memory");\
    if (!_d) {                                                                 \
        asm volatile("{\n\t.reg .pred P1;\n\t"                                 \
            "WL_%=:\n\t"                                                       \
            "mbarrier.try_wait.parity.acquire.cluster.shared::cta.b64 P1, [%0], %1, 0x989680;\n\t" \
            "@P1 bra.uni WD_%=;\n\t"                                           \
            "bra.uni WL_%=;\n\t"                                               \
            "WD_%=:\n\t}" :: "r"(_a), "r"(_p) : "memory");                     \
    }                                                                          \
} while (0)

#if USE_TC
#define TALLOC_CG2(sres, n) \
    asm volatile("tcgen05.alloc.cta_group::2.sync.aligned.shared::cta.b32 [%0], %1;" \
                 :: "r"(sres), "r"(n) : "memory")
#define TDEALLOC_CG2(t, n) \
    asm volatile("tcgen05.dealloc.cta_group::2.sync.aligned.b32 %0, %1;" :: "r"(t), "r"(n))
#define TRELINQ_CG2() \
    asm volatile("tcgen05.relinquish_alloc_permit.cta_group::2.sync.aligned;")
#define TCOMMIT_MC(a, m) \
    asm volatile("tcgen05.commit.cta_group::2.mbarrier::arrive::one.shared::cluster.multicast::cluster.b64 [%0], %1;" \
                 :: "r"(a), "h"((uint16_t)(m)) : "memory")
#define TFENCE_B() asm volatile("tcgen05.fence::before_thread_sync;" ::: "memory")
#define TFENCE_A() asm volatile("tcgen05.fence::after_thread_sync;" ::: "memory")
#define TWAIT_LD() asm volatile("tcgen05.wait::ld.sync.aligned;" ::: "memory")
#define FENCE_ASYNC() asm volatile("fence.proxy.async.shared::cta;" ::: "memory")

#define TCG_LD_X32(r, ta) \
    asm volatile( \
        "tcgen05.ld.sync.aligned.32x32b.x32.b32 " \
        "{%0, %1, %2, %3, %4, %5, %6, %7, " \
        " %8, %9, %10, %11, %12, %13, %14, %15, " \
        " %16, %17, %18, %19, %20, %21, %22, %23, " \
        " %24, %25, %26, %27, %28, %29, %30, %31}, [%32];" \
        : "=r"((r)[0]),  "=r"((r)[1]),  "=r"((r)[2]),  "=r"((r)[3]), \
          "=r"((r)[4]),  "=r"((r)[5]),  "=r"((r)[6]),  "=r"((r)[7]), \
          "=r"((r)[8]),  "=r"((r)[9]),  "=r"((r)[10]), "=r"((r)[11]), \
          "=r"((r)[12]), "=r"((r)[13]), "=r"((r)[14]), "=r"((r)[15]), \
          "=r"((r)[16]), "=r"((r)[17]), "=r"((r)[18]), "=r"((r)[19]), \
          "=r"((r)[20]), "=r"((r)[21]), "=r"((r)[22]), "=r"((r)[23]), \
          "=r"((r)[24]), "=r"((r)[25]), "=r"((r)[26]), "=r"((r)[27]), \
          "=r"((r)[28]), "=r"((r)[29]), "=r"((r)[30]), "=r"((r)[31]) \
        : "r"(ta))

// K-major SW128 descriptor: layout=SW128, version=1, SBO=64, LBO=1
__device__ __forceinline__ uint64_t sdesc(uint32_t a) {
    const uint64_t base = (2ull << 61) | (1ull << 46) | (64ull << 32) | (1ull << 16);
    return base | ((uint64_t)(a >> 4) & 0x3FFFull);
}
// cg2 SS fp8 MMA: D[256, 256] fp32 (+)= A[256,32] * B[256,32]^T (e4m3)
__device__ __forceinline__ void mma_f8_ss_cg2(uint32_t d, uint64_t ad, uint64_t bd,
                                              uint32_t en) {
    asm volatile(
        "{\n\t.reg .pred p;\n\t"
        "setp.ne.u32 p, %4, 0;\n\t"
        "tcgen05.mma.cta_group::2.kind::f8f6f4 [%0], %1, %2, %3, "
        "{%5, %5, %5, %5, %5, %5, %5, %5}, p;\n\t"
        "}"
        :: "r"(d), "l"(ad), "l"(bd), "r"(IDESC_F8_CG2), "r"(en), "r"(0u)
        : "memory");
}
#endif  // USE_TC

__device__ __forceinline__ float fp8tof(uint8_t b) {
    __half_raw h = __nv_cvt_fp8_to_halfraw((__nv_fp8_storage_t)b, __NV_E4M3);
    return __half2float(h);
}
// pack 4 floats -> 4 e4m3 bytes (little-endian order x0..x3)
__device__ __forceinline__ uint32_t pk4(float x0, float x1, float x2, float x3) {
    unsigned short lo, hi;
    asm("cvt.rn.satfinite.e4m3x2.f32 %0, %1, %2;" : "=h"(lo) : "f"(x1), "f"(x0));
    asm("cvt.rn.satfinite.e4m3x2.f32 %0, %1, %2;" : "=h"(hi) : "f"(x3), "f"(x2));
    return (uint32_t)lo | ((uint32_t)hi << 16);
}

// ------------ A converter (self-detecting label dtype; 16 rows/block) ------------
__global__ void conv_A(const float* __restrict__ hs, const void* __restrict__ lab) {
    // per-block int64-vs-int32 detection (labels in [0, 2^31): odd words 0/-1 iff i64)
    const int* lp = (const int*)lab;
    int is64 = 1;
    #pragma unroll 4
    for (int i = 1; i < 256; i += 2) {
        int v = lp[i];
        if (v != 0 && v != -1) { is64 = 0; break; }
    }
    const int n0 = blockIdx.x * 16;
    const int tid = threadIdx.x;
    #pragma unroll 1
    for (int i = 0; i < 16; ++i) {
        const int n = n0 + i;
        uint2* dst = (uint2*)(g_A + (size_t)n * HDIM) + tid;   // 8 fp8 per thread
        if (n < NTOK) {
            const int b = n / (SEQL - 1);
            const int s = n % (SEQL - 1);
            const float4* src = (const float4*)(hs + ((size_t)b * SEQL + s) * HDIM) + tid * 2;
            float4 x = src[0], y = src[1];
            uint2 o;
            o.x = pk4(x.x, x.y, x.z, x.w);
            o.y = pk4(y.x, y.y, y.z, y.w);
            *dst = o;
            if (tid == i) {
                size_t idx = (size_t)b * SEQL + s + 1;
                int v = is64 ? (int)((const long long*)lab)[idx] : ((const int*)lab)[idx];
                g_lab[n] = v;
            }
        } else {
            uint2 z = {0, 0};
            *dst = z;
            if (tid == i) g_lab[n] = -100;
        }
    }
}

__global__ void conv_W(const float* __restrict__ w) {
    const int v0 = blockIdx.x * 16;
    const int c  = threadIdx.x & 127;      // column chunk (16 elems)
    const int hr = threadIdx.x >> 7;       // 0/1: row within pair
    #pragma unroll 1
    for (int i = 0; i < 8; ++i) {
        const size_t v = (size_t)v0 + i * 2 + hr;
        const float4* src = (const float4*)(w + v * HDIM) + c * 4;
        float4 a = src[0], b = src[1], cc = src[2], d = src[3];
        uint4 o;
        o.x = pk4(a.x * WSCALE, a.y * WSCALE, a.z * WSCALE, a.w * WSCALE);
        o.y = pk4(b.x * WSCALE, b.y * WSCALE, b.z * WSCALE, b.w * WSCALE);
        o.z = pk4(cc.x * WSCALE, cc.y * WSCALE, cc.z * WSCALE, cc.w * WSCALE);
        o.w = pk4(d.x * WSCALE, d.y * WSCALE, d.z * WSCALE, d.w * WSCALE);
        ((uint4*)(g_W + v * HDIM))[c] = o;
    }
}

// ------------ fused GEMM + online softmax (cg2 pairs, superstaged) ------------
__global__ void __launch_bounds__(THREADS, 1) __cluster_dims__(2, 1, 1)
fce_main(const float* __restrict__ bias_g) {
    extern __shared__ char smraw[];
    char* smc = (char*)(((uintptr_t)smraw + 1023) & ~(uintptr_t)1023);
    const int tid = threadIdx.x;
    const int tt  = blockIdx.x;    // token tile (one per CTA)
    const int grp = blockIdx.y;    // vocab group

#if USE_TC
    const uint32_t sb    = smaddr(smc);
    const uint32_t sctrl = sb + OFF_CTRL;
    const int wid = tid >> 5;
    const uint32_t rank = cluster_rank();

    // ctrl: tmem@+0, bLF[3]@+8, bGF[3]@+32, bEM[3]@+56, bMF[2]@+80, bME[2]@+96
    const uint32_t bLF = sctrl + 8;
    const uint32_t bGF = sctrl + 32;
    const uint32_t bEM = sctrl + 56;
    const uint32_t bMF = sctrl + 80;
    const uint32_t bME = sctrl + 96;

    if (tid == 0) {
        #pragma unroll
        for (int s = 0; s < NSTG; ++s) {
            MBAR_INIT(bLF + 8 * s, 64);   // 64 producer threads (local)
            MBAR_INIT(bGF + 8 * s, 2);    // 2 relays (leader-side used)
            MBAR_INIT(bEM + 8 * s, 1);    // commit multicast
        }
        MBAR_INIT(bMF + 0, 1);
        MBAR_INIT(bMF + 8, 1);
        MBAR_INIT(bME + 0, 256);          // 2x128 epilogue threads (leader-side)
        MBAR_INIT(bME + 8, 256);
    }
    if (wid == 4) TALLOC_CG2(sctrl, 512);
    __syncthreads();
    CLUSTER_SYNC();                       // barriers visible cluster-wide
    const uint32_t tmem = *(volatile uint32_t*)(smc + OFF_CTRL);

    if (wid >= 6) {
        // ---------- producers: warp 6 = A (32 thr), warp 7 = W-half (32 thr) ----------
        const bool isA = (tid < 224);
        const int p = isA ? (tid - 192) : (tid - 224);     // 0..31
        const int colx = p & 7;
        const int r0 = p >> 3;                              // 0..3
        const uint32_t dstOff = (uint32_t)(isA ? 0 : 16384);
        const char* Ab = (const char*)g_A + (size_t)tt * 128 * HDIM;
        const char* Wb = (const char*)g_W + ((size_t)grp * VPG + (size_t)rank * 128) * HDIM;
        const char* srcBase0 = (isA ? Ab : Wb) + (size_t)r0 * HDIM + (size_t)colx * 16;

        int slot = 0;
        int eph0 = 0, eph1 = 0, eph2 = 0;
        for (int g = 0; g < NSUP_TOT; ++g) {
            const int t = g >> 3, s = g & 7;
            if (g >= NSTG) {
                if (slot == 0)      { MBAR_WAIT(bEM + 0,  (uint32_t)eph0); eph0 ^= 1; }
                else if (slot == 1) { MBAR_WAIT(bEM + 8,  (uint32_t)eph1); eph1 ^= 1; }
                else                { MBAR_WAIT(bEM + 16, (uint32_t)eph2); eph2 ^= 1; }
            }
            const uint32_t stg = sb + (uint32_t)slot * SSTG + dstOff;
            const char* srcT = srcBase0 + (isA ? 0 : (size_t)t * 256 * HDIM);
            #pragma unroll
            for (int sub = 0; sub < 2; ++sub) {
                const char* src = srcT + (size_t)(s * 2 + sub) * KC;
                const uint32_t d0 = stg + (uint32_t)sub * 32768u;
                int r = r0;
                #pragma unroll
                for (int j = 0; j < 32; ++j) {
                    cp16(d0 + (uint32_t)r * 128u + (uint32_t)((colx ^ (r & 7)) << 4), src);
                    src += (size_t)4 * HDIM;
                    r += 4;
                }
            }
            CPASYNC_MBAR_ARRIVE(bLF + 8 * slot);
            slot = (slot == 2) ? 0 : slot + 1;
        }
    } else if (wid == 5) {
        // ---------- relay (1 thread per CTA): local-full -> leader global-full ----------
        if (tid == 160) {
            int slot = 0;
            int lph0 = 0, lph1 = 0, lph2 = 0;
            for (int g = 0; g < NSUP_TOT; ++g) {
                if (slot == 0)      { MBAR_WAIT(bLF + 0,  (uint32_t)lph0); lph0 ^= 1; }
                else if (slot == 1) { MBAR_WAIT(bLF + 8,  (uint32_t)lph1); lph1 ^= 1; }
                else                { MBAR_WAIT(bLF + 16, (uint32_t)lph2); lph2 ^= 1; }
                MBAR_ARRIVE_LEADER(bGF + 8 * slot);
                slot = (slot == 2) ? 0 : slot + 1;
            }
        }
    } else if (wid == 4) {
        // ---------- MMA issue: leader CTA, single thread ----------
        if (tid == 128 && rank == 0) {
            uint64_t da[NSTG], dw[NSTG];
            #pragma unroll
            for (int s = 0; s < NSTG; ++s) {
                da[s] = sdesc(sb + s * SSTG);
                dw[s] = sdesc(sb + s * SSTG + 16384);
            }
            int slot = 0;
            int fph0 = 0, fph1 = 0, fph2 = 0;
            for (int g = 0; g < NSUP_TOT; ++g) {
                const int t = g >> 3, s = g & 7;
                if (s == 0 && t >= 2) {
                    MBAR_WAIT_CL(bME + 8 * (t & 1), (uint32_t)(((t >> 1) - 1) & 1));
                    TFENCE_A();
                }
                if (slot == 0)      { MBAR_WAIT_CL(bGF + 0,  (uint32_t)fph0); fph0 ^= 1; }
                else if (slot == 1) { MBAR_WAIT_CL(bGF + 8,  (uint32_t)fph1); fph1 ^= 1; }
                else                { MBAR_WAIT_CL(bGF + 16, (uint32_t)fph2); fph2 ^= 1; }
                FENCE_ASYNC();
                const uint32_t d = tmem + (uint32_t)(t & 1) * 256u;
                #pragma unroll
                for (int sub = 0; sub < 2; ++sub) {
                    #pragma unroll
                    for (int kc = 0; kc < 4; ++kc) {
                        const uint32_t en = (s == 0 && sub == 0 && kc == 0) ? 0u : 1u;
                        mma_f8_ss_cg2(d, da[slot] + sub * 2048 + kc * 2,
                                         dw[slot] + sub * 2048 + kc * 2, en);
                    }
                }
                TCOMMIT_MC(bEM + 8 * slot, 3);
                if (s == 7) TCOMMIT_MC(bMF + 8 * (t & 1), 3);
                slot = (slot == 2) ? 0 : slot + 1;
            }
        }
    } else {
        // ---------- epilogue (warps 0-3): 1 thread = 1 token row (own TMEM half) ----------
        const int gtok = tt * 128 + tid;
        const int lab = g_lab[gtok];
        float m = -1e30f, ssum = 0.f, tl2 = 0.f;
        const float SCL = INVWS * LOG2E;

        for (int t = 0; t < NTILES; ++t) {
            const int vbase = grp * VPG + t * NTILE;
            float* sbias = (float*)(smc + OFF_BIAS + (t & 1) * 1024);
            if (tid < 64) {
                float4 bv = *(const float4*)(bias_g + vbase + tid * 4);
                bv.x *= LOG2E; bv.y *= LOG2E; bv.z *= LOG2E; bv.w *= LOG2E;
                *(float4*)(sbias + tid * 4) = bv;
            }
            asm volatile("bar.sync 3, 128;" ::: "memory");

            MBAR_WAIT(bMF + 8 * (t & 1), (uint32_t)((t >> 1) & 1));
            TFENCE_A();

            const int labloc = lab - vbase;
            const int labb = labloc >> 5;
            const int labj = labloc & 31;
            const uint32_t dbase = tmem + (uint32_t)(t & 1) * 256u;
            for (int b = 0; b < 8; ++b) {
                uint32_t r[32];
                TCG_LD_X32(r, dbase + (uint32_t)(b * 32));
                TWAIT_LD();
                float bm = -1e30f;
                float l[32];
                #pragma unroll
                for (int j = 0; j < 32; ++j) {
                    l[j] = fmaf(__uint_as_float(r[j]), SCL, sbias[b * 32 + j]);
                    bm = fmaxf(bm, l[j]);
                }
                if (b == labb) {
                    #pragma unroll
                    for (int j = 0; j < 32; ++j)
                        if (j == labj) tl2 = l[j];
                }
                const float nm = fmaxf(m, bm);
                float acc = 0.f;
                #pragma unroll
                for (int j = 0; j < 32; ++j) acc += ex2f(l[j] - nm);
                ssum = ssum * ex2f(m - nm) + acc;
                m = nm;
            }
            TFENCE_B();
            MBAR_ARRIVE_LEADER(bME + 8 * (t & 1));
        }
        g_pm[grp][gtok] = m;      // log2 domain
        g_ps[grp][gtok] = ssum;
        g_pt[grp][gtok] = tl2;    // log2 domain
    }

    __syncthreads();
    CLUSTER_SYNC();               // all reads of peer SMEM / TMEM complete
    if (wid == 4) {
        TRELINQ_CG2();
        TDEALLOC_CG2(tmem, 512);
    }
    CLUSTER_SYNC();
#else
    // ===== fallback (compute_103 PTX pass only; never selected on GB300) =====
    if (tid < 128) {
        const int gtok = tt * 128 + tid;
        const int lab = g_lab[gtok];
        const uint8_t* arow = g_A + (size_t)gtok * HDIM;
        float m = -1e30f, ssum = 0.f, tl2 = 0.f;
        for (int v = 0; v < VPG; ++v) {
            const int vg = grp * VPG + v;
            const uint8_t* wrow = g_W + (size_t)vg * HDIM;
            float acc = 0.f;
            for (int k = 0; k < HDIM; ++k)
                acc += fp8tof(arow[k]) * fp8tof(wrow[k]);
            float l2 = (acc * INVWS + bias_g[vg]) * LOG2E;
            if (vg == lab) tl2 = l2;
            float nm = fmaxf(m, l2);
            ssum = ssum * ex2f(m - nm) + ex2f(l2 - nm);
            m = nm;
        }
        g_pm[grp][gtok] = m;
        g_ps[grp][gtok] = ssum;
        g_pt[grp][gtok] = tl2;
    }
#endif
}

// ------------ single-kernel combine: 256 threads, 32 tokens each ------------
__global__ void combine(float* __restrict__ out) {
    __shared__ double sh[256];
    __shared__ int shc[256];
    const int tid = threadIdx.x;
    double sum = 0.0;
    int cnt = 0;
    #pragma unroll 4
    for (int k = 0; k < 32; ++k) {
        const int i = tid + k * 256;
        const int lab = g_lab[i];
        if (lab < 0) continue;
        const float m0 = g_pm[0][i], m1 = g_pm[1][i];
        const float M = fmaxf(m0, m1);
        const float S = g_ps[0][i] * exp2f(m0 - M) + g_ps[1][i] * exp2f(m1 - M);
        const float lse2 = M + log2f(S);
        const float tl2 = g_pt[0][i] + g_pt[1][i];
        sum += (double)(lse2 - tl2);
        cnt++;
    }
    sh[tid] = sum;
    shc[tid] = cnt;
    __syncthreads();
    for (int o = 128; o > 0; o >>= 1) {
        if (tid < (unsigned)o) {
            sh[tid] += sh[tid + o];
            shc[tid] += shc[tid + o];
        }
        __syncthreads();
    }
    if (tid == 0)
        out[0] = (float)(sh[0] * LN2 / (double)(shc[0] > 0 ? shc[0] : 1));
}

namespace {
struct WarmLoad {
    WarmLoad() {
        void* p = nullptr;
        cudaGetSymbolAddress(&p, g_W);
        (void)p;
    }
};
static WarmLoad s_warm;
}

extern "C" void kernel_launch(void* const* d_in, const int* in_sizes, int n_in,
                              void* d_out, int out_size) {
    (void)in_sizes; (void)n_in; (void)out_size;
    const float* hs   = (const float*)d_in[0];
    const void*  lab  = d_in[1];
    const float* w    = (const float*)d_in[2];
    const float* bias = (const float*)d_in[3];
    float* out = (float*)d_out;

    // lazy-created side stream + events (first call is the uncaptured
    // correctness run, so creation happens outside graph capture)
    static cudaStream_t s2 = nullptr;
    static cudaEvent_t ev0 = nullptr, ev2 = nullptr;
    if (s2 == nullptr) {
        cudaStreamCreateWithFlags(&s2, cudaStreamNonBlocking);
        cudaEventCreateWithFlags(&ev0, cudaEventDisableTiming);
        cudaEventCreateWithFlags(&ev2, cudaEventDisableTiming);
    }

    cudaFuncSetAttribute(fce_main, cudaFuncAttributeMaxDynamicSharedMemorySize, SMEM_DYN);

    // fork: conv_W (big, DRAM-bound) overlaps conv_A (small). Both complete
    // before fce_main — no overlap with the cluster kernel (R12 lesson).
    cudaEventRecord(ev0, 0);
    cudaStreamWaitEvent(s2, ev0, 0);
    conv_W<<<VOCABN / 16, 256, 0, s2>>>(w);

    conv_A<<<NTOKP / 16, 256>>>(hs, lab);

    cudaEventRecord(ev2, s2);
    cudaStreamWaitEvent(0, ev2, 0);

    fce_main<<<dim3(64, 2), THREADS, SMEM_DYN>>>(bias);
    combine<<<1, 256>>>(out);
}

// round 16
// speedup vs baseline: 1.0280x; 1.0280x over previous
#include <cuda_runtime.h>
#include <cuda_bf16.h>
#include <cuda_fp8.h>
#include <stdint.h>

#define HDIM   2048
#define SEQL   2048
#define NTOK   8188
#define NTOKP  8192
#define VOCABN 131072
#define NGRP   2
#define VPG    65536
#define NTILE  256
#define NTILES 256          // VPG / NTILE
#define KC     128          // K elems per kstep (128B rows, fp8)
#define KSTEPS 16           // HDIM / KC
#define NSUP   8            // superstages per tile (2 ksteps each)
#define NSTG   3            // slots
#define SSTG   65536        // per-slot bytes: A0 16K | W0 16K | A1 16K | W1 16K
#define THREADS 256
#define NSUP_TOT (NTILES * NSUP)   // 2048
#define NCB    32           // combine blocks

#define WSCALE 32.0f
#define INVWS  0.03125f
#define LOG2E  1.44269504f
#define LN2    0.6931471805599453

#define OFF_BIAS  196608    // 2 x 1KB bias double buffer (pre-scaled by log2e)
#define OFF_CTRL  198656    // tmem ptr + mbarriers
#define SMEM_DYN  (198912 + 1024)

// idesc kind::f8f6f4: dtype F32 (bit4), e4m3, N=256 -> (32<<17), M=256 -> (2<<27)
#define IDESC_F8_CG2 0x10400010u

#if defined(__CUDA_ARCH_FEAT_SM103_ALL) || defined(__CUDA_ARCH_FEAT_SM100_ALL) || defined(__CUDA_ARCH_FEAT_SM101_ALL)
#define USE_TC 1
#else
#define USE_TC 0
#endif

// ------------ device scratch (static; allocation-free) ------------
__device__ uint8_t g_A[(size_t)NTOKP * HDIM];    // fp8 e4m3
__device__ uint8_t g_W[(size_t)VOCABN * HDIM];   // fp8 e4m3, pre-scaled by 32
__device__ int    g_lab[NTOKP];
__device__ float  g_pm[NGRP][NTOKP];
__device__ float  g_ps[NGRP][NTOKP];
__device__ float  g_pt[NGRP][NTOKP];  // log2-domain target logit
__device__ double g_part[NCB];
__device__ int    g_pcnt[NCB];

// ------------ PTX helpers ------------
__device__ __forceinline__ uint32_t smaddr(const void* p) {
    return (uint32_t)__cvta_generic_to_shared(p);
}
__device__ __forceinline__ float ex2f(float x) {
    float y;
    asm("ex2.approx.ftz.f32 %0, %1;" : "=f"(y) : "f"(x));
    return y;
}
__device__ __forceinline__ void cp16(uint32_t dst, const void* src) {
    asm volatile("cp.async.cg.shared.global [%0], [%1], 16;" :: "r"(dst), "l"(src) : "memory");
}
__device__ __forceinline__ uint32_t cluster_rank() {
    uint32_t r;
    asm("mov.u32 %0, %%cluster_ctarank;" : "=r"(r));
    return r;
}
#define CLUSTER_SYNC() do { \
    asm volatile("barrier.cluster.arrive.aligned;" ::: "memory"); \
    asm volatile("barrier.cluster.wait.aligned;" ::: "memory"); \
} while (0)

#define MBAR_INIT(a, c) \
    asm volatile("mbarrier.init.shared.b64 [%0], %1;" :: "r"(a), "r"(c) : "memory")
#define CPASYNC_MBAR_ARRIVE(a) \
    asm volatile("cp.async.mbarrier.arrive.noinc.shared::cta.b64 [%0];" :: "r"(a) : "memory")
// arrive on the LEADER CTA's barrier of the MMA pair (clear bit 24)
#define MBAR_ARRIVE_LEADER(a) \
    asm volatile("{\n\t.reg .b32 la;\n\tand.b32 la, %0, 0xFEFFFFFF;\n\t" \
                 "mbarrier.arrive.shared::cluster.b64 _, [la];\n\t}" \
                 :: "r"(a) : "memory")

#define MBAR_WAIT(addr, ph) do {                                               \
    uint32_t _a = (addr); uint32_t _p = (ph); uint32_t _d;                     \
    asm volatile("{\n\t.reg .pred p;\n\t"                                      \
        "mbarrier.try_wait.parity.acquire.cta.shared::cta.b64 p, [%1], %2;\n\t"\
        "selp.b32 %0, 1, 0, p;\n\t}" : "=r"(_d) : "r"(_a), "r"(_p) : "memory");\
    if (!_d) {                                                                 \
        asm volatile("{\n\t.reg .pred P1;\n\t"                                 \
            "WL_%=:\n\t"                                                       \
            "mbarrier.try_wait.parity.acquire.cta.shared::cta.b64 P1, [%0], %1, 0x989680;\n\t" \
            "@P1 bra.uni WD_%=;\n\t"                                           \
            "bra.uni WL_%=;\n\t"                                               \
            "WD_%=:\n\t}" :: "r"(_a), "r"(_p) : "memory");                     \
    }                                                                          \
} while (0)

// cluster-scope acquire (cross-CTA release/acquire pairing)
#define MBAR_WAIT_CL(addr, ph) do {                                            \
    uint32_t _a = (addr); uint32_t _p = (ph); uint32_t _d;                     \
    asm volatile("{\n\t.reg .pred p;\n\t"                                      \
        "mbarrier.try_wait.parity.acquire.cluster.shared::cta.b64 p, [%1], %2;\n\t"\
        "selp.b32 %0, 1, 0, p;\n\t}" : "=r"(_d) : "r"(_a), "r"(_p) : "memory");\
    if (!_d) {                                                                 \
        asm volatile("{\n\t.reg .pred P1;\n\t"                                 \
            "WL_%=:\n\t"                                                       \
            "mbarrier.try_wait.parity.acquire.cluster.shared::cta.b64 P1, [%0], %1, 0x989680;\n\t" \
            "@P1 bra.uni WD_%=;\n\t"                                           \
            "bra.uni WL_%=;\n\t"                                               \
            "WD_%=:\n\t}" :: "r"(_a), "r"(_p) : "memory");                     \
    }                                                                          \
} while (0)

#if USE_TC
#define TALLOC_CG2(sres, n) \
    asm volatile("tcgen05.alloc.cta_group::2.sync.aligned.shared::cta.b32 [%0], %1;" \
                 :: "r"(sres), "r"(n) : "memory")
#define TDEALLOC_CG2(t, n) \
    asm volatile("tcgen05.dealloc.cta_group::2.sync.aligned.b32 %0, %1;" :: "r"(t), "r"(n))
#define TRELINQ_CG2() \
    asm volatile("tcgen05.relinquish_alloc_permit.cta_group::2.sync.aligned;")
#define TCOMMIT_MC(a, m) \
    asm volatile("tcgen05.commit.cta_group::2.mbarrier::arrive::one.shared::cluster.multicast::cluster.b64 [%0], %1;" \
                 :: "r"(a), "h"((uint16_t)(m)) : "memory")
#define TFENCE_B() asm volatile("tcgen05.fence::before_thread_sync;" ::: "memory")
#define TFENCE_A() asm volatile("tcgen05.fence::after_thread_sync;" ::: "memory")
#define TWAIT_LD() asm volatile("tcgen05.wait::ld.sync.aligned;" ::: "memory")
#define FENCE_ASYNC() asm volatile("fence.proxy.async.shared::cta;" ::: "memory")

#define TCG_LD_X32(r, ta) \
    asm volatile( \
        "tcgen05.ld.sync.aligned.32x32b.x32.b32 " \
        "{%0, %1, %2, %3, %4, %5, %6, %7, " \
        " %8, %9, %10, %11, %12, %13, %14, %15, " \
        " %16, %17, %18, %19, %20, %21, %22, %23, " \
        " %24, %25, %26, %27, %28, %29, %30, %31}, [%32];" \
        : "=r"((r)[0]),  "=r"((r)[1]),  "=r"((r)[2]),  "=r"((r)[3]), \
          "=r"((r)[4]),  "=r"((r)[5]),  "=r"((r)[6]),  "=r"((r)[7]), \
          "=r"((r)[8]),  "=r"((r)[9]),  "=r"((r)[10]), "=r"((r)[11]), \
          "=r"((r)[12]), "=r"((r)[13]), "=r"((r)[14]), "=r"((r)[15]), \
          "=r"((r)[16]), "=r"((r)[17]), "=r"((r)[18]), "=r"((r)[19]), \
          "=r"((r)[20]), "=r"((r)[21]), "=r"((r)[22]), "=r"((r)[23]), \
          "=r"((r)[24]), "=r"((r)[25]), "=r"((r)[26]), "=r"((r)[27]), \
          "=r"((r)[28]), "=r"((r)[29]), "=r"((r)[30]), "=r"((r)[31]) \
        : "r"(ta))

// K-major SW128 descriptor: layout=SW128, version=1, SBO=64, LBO=1
__device__ __forceinline__ uint64_t sdesc(uint32_t a) {
    const uint64_t base = (2ull << 61) | (1ull << 46) | (64ull << 32) | (1ull << 16);
    return base | ((uint64_t)(a >> 4) & 0x3FFFull);
}
// cg2 SS fp8 MMA: D[256, 256] fp32 (+)= A[256,32] * B[256,32]^T (e4m3)
__device__ __forceinline__ void mma_f8_ss_cg2(uint32_t d, uint64_t ad, uint64_t bd,
                                              uint32_t en) {
    asm volatile(
        "{\n\t.reg .pred p;\n\t"
        "setp.ne.u32 p, %4, 0;\n\t"
        "tcgen05.mma.cta_group::2.kind::f8f6f4 [%0], %1, %2, %3, "
        "{%5, %5, %5, %5, %5, %5, %5, %5}, p;\n\t"
        "}"
        :: "r"(d), "l"(ad), "l"(bd), "r"(IDESC_F8_CG2), "r"(en), "r"(0u)
        : "memory");
}
#endif  // USE_TC

__device__ __forceinline__ float fp8tof(uint8_t b) {
    __half_raw h = __nv_cvt_fp8_to_halfraw((__nv_fp8_storage_t)b, __NV_E4M3);
    return __half2float(h);
}
// pack 4 floats -> 4 e4m3 bytes (little-endian order x0..x3)
__device__ __forceinline__ uint32_t pk4(float x0, float x1, float x2, float x3) {
    unsigned short lo, hi;
    asm("cvt.rn.satfinite.e4m3x2.f32 %0, %1, %2;" : "=h"(lo) : "f"(x1), "f"(x0));
    asm("cvt.rn.satfinite.e4m3x2.f32 %0, %1, %2;" : "=h"(hi) : "f"(x3), "f"(x2));
    return (uint32_t)lo | ((uint32_t)hi << 16);
}

// ------------ A converter (self-detecting label dtype; 16 rows/block) ------------
__global__ void conv_A(const float* __restrict__ hs, const void* __restrict__ lab) {
    // per-block int64-vs-int32 detection (labels in [0, 2^31): odd words 0/-1 iff i64)
    const int* lp = (const int*)lab;
    int is64 = 1;
    #pragma unroll 4
    for (int i = 1; i < 256; i += 2) {
        int v = lp[i];
        if (v != 0 && v != -1) { is64 = 0; break; }
    }
    const int n0 = blockIdx.x * 16;
    const int tid = threadIdx.x;
    #pragma unroll 1
    for (int i = 0; i < 16; ++i) {
        const int n = n0 + i;
        uint2* dst = (uint2*)(g_A + (size_t)n * HDIM) + tid;   // 8 fp8 per thread
        if (n < NTOK) {
            const int b = n / (SEQL - 1);
            const int s = n % (SEQL - 1);
            const float4* src = (const float4*)(hs + ((size_t)b * SEQL + s) * HDIM) + tid * 2;
            float4 x = src[0], y = src[1];
            uint2 o;
            o.x = pk4(x.x, x.y, x.z, x.w);
            o.y = pk4(y.x, y.y, y.z, y.w);
            *dst = o;
            if (tid == i) {
                size_t idx = (size_t)b * SEQL + s + 1;
                int v = is64 ? (int)((const long long*)lab)[idx] : ((const int*)lab)[idx];
                g_lab[n] = v;
            }
        } else {
            uint2 z = {0, 0};
            *dst = z;
            if (tid == i) g_lab[n] = -100;
        }
    }
}

__global__ void conv_W(const float* __restrict__ w) {
    const int v0 = blockIdx.x * 16;
    const int c  = threadIdx.x & 127;      // column chunk (16 elems)
    const int hr = threadIdx.x >> 7;       // 0/1: row within pair
    #pragma unroll 1
    for (int i = 0; i < 8; ++i) {
        const size_t v = (size_t)v0 + i * 2 + hr;
        const float4* src = (const float4*)(w + v * HDIM) + c * 4;
        float4 a = src[0], b = src[1], cc = src[2], d = src[3];
        uint4 o;
        o.x = pk4(a.x * WSCALE, a.y * WSCALE, a.z * WSCALE, a.w * WSCALE);
        o.y = pk4(b.x * WSCALE, b.y * WSCALE, b.z * WSCALE, b.w * WSCALE);
        o.z = pk4(cc.x * WSCALE, cc.y * WSCALE, cc.z * WSCALE, cc.w * WSCALE);
        o.w = pk4(d.x * WSCALE, d.y * WSCALE, d.z * WSCALE, d.w * WSCALE);
        ((uint4*)(g_W + v * HDIM))[c] = o;
    }
}

// ------------ fused GEMM + online softmax (cg2 pairs, superstaged) ------------
__global__ void __launch_bounds__(THREADS, 1) __cluster_dims__(2, 1, 1)
fce_main(const float* __restrict__ bias_g) {
    extern __shared__ char smraw[];
    char* smc = (char*)(((uintptr_t)smraw + 1023) & ~(uintptr_t)1023);
    const int tid = threadIdx.x;
    const int tt  = blockIdx.x;    // token tile (one per CTA)
    const int grp = blockIdx.y;    // vocab group

#if USE_TC
    const uint32_t sb    = smaddr(smc);
    const uint32_t sctrl = sb + OFF_CTRL;
    const int wid = tid >> 5;
    const uint32_t rank = cluster_rank();

    // ctrl: tmem@+0, bLF[3]@+8, bGF[3]@+32, bEM[3]@+56, bMF[2]@+80, bME[2]@+96
    const uint32_t bLF = sctrl + 8;
    const uint32_t bGF = sctrl + 32;
    const uint32_t bEM = sctrl + 56;
    const uint32_t bMF = sctrl + 80;
    const uint32_t bME = sctrl + 96;

    if (tid == 0) {
        #pragma unroll
        for (int s = 0; s < NSTG; ++s) {
            MBAR_INIT(bLF + 8 * s, 64);   // 64 producer threads (local)
            MBAR_INIT(bGF + 8 * s, 2);    // 2 relays (leader-side used)
            MBAR_INIT(bEM + 8 * s, 1);    // commit multicast
        }
        MBAR_INIT(bMF + 0, 1);
        MBAR_INIT(bMF + 8, 1);
        MBAR_INIT(bME + 0, 256);          // 2x128 epilogue threads (leader-side)
        MBAR_INIT(bME + 8, 256);
    }
    if (wid == 4) TALLOC_CG2(sctrl, 512);
    __syncthreads();
    CLUSTER_SYNC();                       // barriers visible cluster-wide
    const uint32_t tmem = *(volatile uint32_t*)(smc + OFF_CTRL);

    if (wid >= 6) {
        // ---------- producers: warp 6 = A (32 thr), warp 7 = W-half (32 thr) ----------
        const bool isA = (tid < 224);
        const int p = isA ? (tid - 192) : (tid - 224);     // 0..31
        const int colx = p & 7;
        const int r0 = p >> 3;                              // 0..3
        const uint32_t dstOff = (uint32_t)(isA ? 0 : 16384);
        const char* Ab = (const char*)g_A + (size_t)tt * 128 * HDIM;
        const char* Wb = (const char*)g_W + ((size_t)grp * VPG + (size_t)rank * 128) * HDIM;
        const char* srcBase0 = (isA ? Ab : Wb) + (size_t)r0 * HDIM + (size_t)colx * 16;

        int slot = 0;
        int eph0 = 0, eph1 = 0, eph2 = 0;
        for (int g = 0; g < NSUP_TOT; ++g) {
            const int t = g >> 3, s = g & 7;
            if (g >= NSTG) {
                if (slot == 0)      { MBAR_WAIT(bEM + 0,  (uint32_t)eph0); eph0 ^= 1; }
                else if (slot == 1) { MBAR_WAIT(bEM + 8,  (uint32_t)eph1); eph1 ^= 1; }
                else                { MBAR_WAIT(bEM + 16, (uint32_t)eph2); eph2 ^= 1; }
            }
            const uint32_t stg = sb + (uint32_t)slot * SSTG + dstOff;
            const char* srcT = srcBase0 + (isA ? 0 : (size_t)t * 256 * HDIM);
            #pragma unroll
            for (int sub = 0; sub < 2; ++sub) {
                const char* src = srcT + (size_t)(s * 2 + sub) * KC;
                const uint32_t d0 = stg + (uint32_t)sub * 32768u;
                int r = r0;
                #pragma unroll
                for (int j = 0; j < 32; ++j) {
                    cp16(d0 + (uint32_t)r * 128u + (uint32_t)((colx ^ (r & 7)) << 4), src);
                    src += (size_t)4 * HDIM;
                    r += 4;
                }
            }
            CPASYNC_MBAR_ARRIVE(bLF + 8 * slot);
            slot = (slot == 2) ? 0 : slot + 1;
        }
    } else if (wid == 5) {
        // ---------- relay (1 thread per CTA): local-full -> leader global-full ----------
        if (tid == 160) {
            int slot = 0;
            int lph0 = 0, lph1 = 0, lph2 = 0;
            for (int g = 0; g < NSUP_TOT; ++g) {
                if (slot == 0)      { MBAR_WAIT(bLF + 0,  (uint32_t)lph0); lph0 ^= 1; }
                else if (slot == 1) { MBAR_WAIT(bLF + 8,  (uint32_t)lph1); lph1 ^= 1; }
                else                { MBAR_WAIT(bLF + 16, (uint32_t)lph2); lph2 ^= 1; }
                MBAR_ARRIVE_LEADER(bGF + 8 * slot);
                slot = (slot == 2) ? 0 : slot + 1;
            }
        }
    } else if (wid == 4) {
        // ---------- MMA issue: leader CTA, single thread ----------
        if (tid == 128 && rank == 0) {
            uint64_t da[NSTG], dw[NSTG];
            #pragma unroll
            for (int s = 0; s < NSTG; ++s) {
                da[s] = sdesc(sb + s * SSTG);
                dw[s] = sdesc(sb + s * SSTG + 16384);
            }
            int slot = 0;
            int fph0 = 0, fph1 = 0, fph2 = 0;
            for (int g = 0; g < NSUP_TOT; ++g) {
                const int t = g >> 3, s = g & 7;
                if (s == 0 && t >= 2) {
                    MBAR_WAIT_CL(bME + 8 * (t & 1), (uint32_t)(((t >> 1) - 1) & 1));
                    TFENCE_A();
                }
                if (slot == 0)      { MBAR_WAIT_CL(bGF + 0,  (uint32_t)fph0); fph0 ^= 1; }
                else if (slot == 1) { MBAR_WAIT_CL(bGF + 8,  (uint32_t)fph1); fph1 ^= 1; }
                else                { MBAR_WAIT_CL(bGF + 16, (uint32_t)fph2); fph2 ^= 1; }
                FENCE_ASYNC();
                const uint32_t d = tmem + (uint32_t)(t & 1) * 256u;
                #pragma unroll
                for (int sub = 0; sub < 2; ++sub) {
                    #pragma unroll
                    for (int kc = 0; kc < 4; ++kc) {
                        const uint32_t en = (s == 0 && sub == 0 && kc == 0) ? 0u : 1u;
                        mma_f8_ss_cg2(d, da[slot] + sub * 2048 + kc * 2,
                                         dw[slot] + sub * 2048 + kc * 2, en);
                    }
                }
                TCOMMIT_MC(bEM + 8 * slot, 3);
                if (s == 7) TCOMMIT_MC(bMF + 8 * (t & 1), 3);
                slot = (slot == 2) ? 0 : slot + 1;
            }
        }
    } else {
        // ---------- epilogue (warps 0-3): 1 thread = 1 token row (own TMEM half) ----------
        const int gtok = tt * 128 + tid;
        const int lab = g_lab[gtok];
        float m = -1e30f, ssum = 0.f, tl2 = 0.f;
        const float SCL = INVWS * LOG2E;

        for (int t = 0; t < NTILES; ++t) {
            const int vbase = grp * VPG + t * NTILE;
            float* sbias = (float*)(smc + OFF_BIAS + (t & 1) * 1024);
            if (tid < 64) {
                float4 bv = *(const float4*)(bias_g + vbase + tid * 4);
                bv.x *= LOG2E; bv.y *= LOG2E; bv.z *= LOG2E; bv.w *= LOG2E;
                *(float4*)(sbias + tid * 4) = bv;
            }
            asm volatile("bar.sync 3, 128;" ::: "memory");

            MBAR_WAIT(bMF + 8 * (t & 1), (uint32_t)((t >> 1) & 1));
            TFENCE_A();

            const int labloc = lab - vbase;
            const int labb = labloc >> 5;
            const int labj = labloc & 31;
            const uint32_t dbase = tmem + (uint32_t)(t & 1) * 256u;
            for (int b = 0; b < 8; ++b) {
                uint32_t r[32];
                TCG_LD_X32(r, dbase + (uint32_t)(b * 32));
                TWAIT_LD();
                float bm = -1e30f;
                float l[32];
                #pragma unroll
                for (int j = 0; j < 32; ++j) {
                    l[j] = fmaf(__uint_as_float(r[j]), SCL, sbias[b * 32 + j]);
                    bm = fmaxf(bm, l[j]);
                }
                if (b == labb) {
                    #pragma unroll
                    for (int j = 0; j < 32; ++j)
                        if (j == labj) tl2 = l[j];
                }
                const float nm = fmaxf(m, bm);
                float acc = 0.f;
                #pragma unroll
                for (int j = 0; j < 32; ++j) acc += ex2f(l[j] - nm);
                ssum = ssum * ex2f(m - nm) + acc;
                m = nm;
            }
            TFENCE_B();
            MBAR_ARRIVE_LEADER(bME + 8 * (t & 1));
        }
        g_pm[grp][gtok] = m;      // log2 domain
        g_ps[grp][gtok] = ssum;
        g_pt[grp][gtok] = tl2;    // log2 domain
    }

    __syncthreads();
    CLUSTER_SYNC();               // all reads of peer SMEM / TMEM complete
    if (wid == 4) {
        TRELINQ_CG2();
        TDEALLOC_CG2(tmem, 512);
    }
    CLUSTER_SYNC();
#else
    // ===== fallback (compute_103 PTX pass only; never selected on GB300) =====
    if (tid < 128) {
        const int gtok = tt * 128 + tid;
        const int lab = g_lab[gtok];
        const uint8_t* arow = g_A + (size_t)gtok * HDIM;
        float m = -1e30f, ssum = 0.f, tl2 = 0.f;
        for (int v = 0; v < VPG; ++v) {
            const int vg = grp * VPG + v;
            const uint8_t* wrow = g_W + (size_t)vg * HDIM;
            float acc = 0.f;
            for (int k = 0; k < HDIM; ++k)
                acc += fp8tof(arow[k]) * fp8tof(wrow[k]);
            float l2 = (acc * INVWS + bias_g[vg]) * LOG2E;
            if (vg == lab) tl2 = l2;
            float nm = fmaxf(m, l2);
            ssum = ssum * ex2f(m - nm) + ex2f(l2 - nm);
            m = nm;
        }
        g_pm[grp][gtok] = m;
        g_ps[grp][gtok] = ssum;
        g_pt[grp][gtok] = tl2;
    }
#endif
}

// ------------ parallel combine: 32 blocks, 1 thread per token ------------
__global__ void combine_part() {
    __shared__ double sh[256];
    __shared__ int shc[256];
    const int i = blockIdx.x * 256 + threadIdx.x;
    double v = 0.0;
    int c = 0;
    if (i < NTOKP) {
        const int lab = g_lab[i];
        if (lab >= 0) {
            const float m0 = g_pm[0][i], m1 = g_pm[1][i];
            const float M = fmaxf(m0, m1);
            const float S = g_ps[0][i] * exp2f(m0 - M) + g_ps[1][i] * exp2f(m1 - M);
            const float lse2 = M + log2f(S);
            const float tl2 = g_pt[0][i] + g_pt[1][i];
            v = (double)(lse2 - tl2);
            c = 1;
        }
    }
    sh[threadIdx.x] = v;
    shc[threadIdx.x] = c;
    __syncthreads();
    for (int o = 128; o > 0; o >>= 1) {
        if (threadIdx.x < (unsigned)o) {
            sh[threadIdx.x] += sh[threadIdx.x + o];
            shc[threadIdx.x] += shc[threadIdx.x + o];
        }
        __syncthreads();
    }
    if (threadIdx.x == 0) {
        g_part[blockIdx.x] = sh[0];
        g_pcnt[blockIdx.x] = shc[0];
    }
}

__global__ void combine_final(float* __restrict__ out) {
    __shared__ double sh[NCB];
    __shared__ int shc[NCB];
    const int t = threadIdx.x;
    sh[t] = g_part[t];
    shc[t] = g_pcnt[t];
    __syncthreads();
    if (t == 0) {
        double s = 0.0;
        int c = 0;
        #pragma unroll
        for (int i = 0; i < NCB; ++i) { s += sh[i]; c += shc[i]; }
        out[0] = (float)(s * LN2 / (double)(c > 0 ? c : 1));
    }
}

namespace {
struct WarmLoad {
    WarmLoad() {
        void* p = nullptr;
        cudaGetSymbolAddress(&p, g_W);
        (void)p;
    }
};
static WarmLoad s_warm;
}

extern "C" void kernel_launch(void* const* d_in, const int* in_sizes, int n_in,
                              void* d_out, int out_size) {
    (void)in_sizes; (void)n_in; (void)out_size;
    const float* hs   = (const float*)d_in[0];
    const void*  lab  = d_in[1];
    const float* w    = (const float*)d_in[2];
    const float* bias = (const float*)d_in[3];
    float* out = (float*)d_out;

    // lazy-created side stream + events (first call is the uncaptured
    // correctness run, so creation happens outside graph capture)
    static cudaStream_t s2 = nullptr;
    static cudaEvent_t ev0 = nullptr, ev2 = nullptr;
    if (s2 == nullptr) {
        cudaStreamCreateWithFlags(&s2, cudaStreamNonBlocking);
        cudaEventCreateWithFlags(&ev0, cudaEventDisableTiming);
        cudaEventCreateWithFlags(&ev2, cudaEventDisableTiming);
    }

    cudaFuncSetAttribute(fce_main, cudaFuncAttributeMaxDynamicSharedMemorySize, SMEM_DYN);

    // fork: conv_W (big, DRAM-bound) overlaps conv_A (small). Both complete
    // before fce_main — no overlap with the cluster kernel (R12 lesson).
    cudaEventRecord(ev0, 0);
    cudaStreamWaitEvent(s2, ev0, 0);
    conv_W<<<VOCABN / 16, 256, 0, s2>>>(w);

    conv_A<<<NTOKP / 16, 256>>>(hs, lab);

    cudaEventRecord(ev2, s2);
    cudaStreamWaitEvent(0, ev2, 0);

    fce_main<<<dim3(64, 2), THREADS, SMEM_DYN>>>(bias);
    combine_part<<<NCB, 256>>>();
    combine_final<<<1, NCB>>>(out);
}